// round 11
// baseline (speedup 1.0000x reference)
#include <cuda_runtime.h>
#include <math_constants.h>

// TropicalConv2D (max-plus 3x3 depthwise), x:(8,64,224,224) f32, k:(64,1,3,3), s=1,p=1,d=1.
// R11: R9 structure + L2 policy via createpolicy/cache_hint (evict_last on x loads,
//      ptxas-legal form for 128-bit loads) + __stcs evict-first output stores.

#define XB 8
#define XC 64
#define XH 224
#define XW 224
#define W4 56          // float4 groups per row
#define RPT 8          // output rows per thread
#define BY 2           // row strips per block
#define ROWS_PER_BLOCK (RPT * BY)               // 16
#define STRIPS (XH / ROWS_PER_BLOCK)            // 14

#define NEG_INF (-CUDART_INF_F)

__device__ __forceinline__ float fmax3(float a, float b, float c) {
    float d;
    asm("max.f32 %0, %1, %2, %3;" : "=f"(d) : "f"(a), "f"(b), "f"(c));
    return d;
}

__device__ __forceinline__ unsigned long long mk_evict_last_policy() {
    unsigned long long p;
    asm("createpolicy.fractional.L2::evict_last.b64 %0, 1.0;" : "=l"(p));
    return p;
}

// x loads: non-coherent + L2 evict_last via cache_hint (pin input in L2).
__device__ __forceinline__ float4 ldg_el_f4(const float* p, unsigned long long pol) {
    float4 v;
    asm volatile("ld.global.nc.L2::cache_hint.v4.f32 {%0,%1,%2,%3}, [%4], %5;"
                 : "=f"(v.x), "=f"(v.y), "=f"(v.z), "=f"(v.w) : "l"(p), "l"(pol));
    return v;
}
__device__ __forceinline__ float ldg_el_f1(const float* p, unsigned long long pol) {
    float v;
    asm volatile("ld.global.nc.L2::cache_hint.f32 %0, [%1], %2;"
                 : "=f"(v) : "l"(p), "l"(pol));
    return v;
}

struct Raw { float v0, v1, v2, v3, l, r; };
struct Win { float w[6]; };   // wl, v0..v3, wr

__device__ __forceinline__ Raw neg_raw() {
    Raw w; w.v0 = w.v1 = w.v2 = w.v3 = w.l = w.r = NEG_INF; return w;
}

// Load stage. CHECK=false (interior strips): no row-range test, no neg_raw path.
template<bool CHECK>
__device__ __forceinline__ Raw load_raw(const float* __restrict__ pp, int r,
                                        int x_eff, bool has_l, bool has_r,
                                        unsigned long long pol) {
    if (CHECK) { if (r < 0 || r >= XH) return neg_raw(); }
    const float* rp = pp + r * XW + x_eff * 4;
    float4 v = ldg_el_f4(rp, pol);
    Raw w;
    w.v0 = v.x; w.v1 = v.y; w.v2 = v.z; w.v3 = v.w;
    w.l = has_l ? ldg_el_f1(rp - 1, pol) : NEG_INF;
    w.r = has_r ? ldg_el_f1(rp + 4, pol) : NEG_INF;
    return w;
}

// Window stage: 2 SHFL + 2 SEL (+1 loop-invariant edge SEL).
__device__ __forceinline__ Win make_win(const Raw& w, int lane, bool right_edge) {
    Win o;
    o.w[1] = w.v0; o.w[2] = w.v1; o.w[3] = w.v2; o.w[4] = w.v3;
    float wl = __shfl_up_sync(0xffffffffu,   w.v3, 1);
    float wr = __shfl_down_sync(0xffffffffu, w.v0, 1);
    o.w[0] = (lane == 0)  ? w.l : wl;
    o.w[5] = (lane == 31) ? w.r : wr;
    if (right_edge) o.w[5] = NEG_INF;
    return o;
}

// Per-window-row horizontal contribution: 3 FADD + 1 FMNMX3 per output.
__device__ __forceinline__ void row_contrib(const Win& w, float k0, float k1, float k2,
                                            float& r0, float& r1, float& r2, float& r3) {
    r0 = fmax3(w.w[0] + k0, w.w[1] + k1, w.w[2] + k2);
    r1 = fmax3(w.w[1] + k0, w.w[2] + k1, w.w[3] + k2);
    r2 = fmax3(w.w[2] + k0, w.w[3] + k1, w.w[4] + k2);
    r3 = fmax3(w.w[3] + k0, w.w[4] + k1, w.w[5] + k2);
}

template<bool CHECK>
__device__ __forceinline__ void run_strip(
    const float* __restrict__ pp, float* __restrict__ op,
    int row0, int x_eff, int lane, bool active, bool right_edge,
    bool has_l, bool has_r, unsigned long long pol,
    float k00, float k01, float k02,
    float k10, float k11, float k12,
    float k20, float k21, float k22)
{
    // Prologue: three independent loads in flight, then resolve first two windows.
    Raw rm = load_raw<CHECK>(pp, row0 - 1, x_eff, has_l, has_r, pol);
    Raw rc = load_raw<CHECK>(pp, row0,     x_eff, has_l, has_r, pol);
    Raw rp = load_raw<CHECK>(pp, row0 + 1, x_eff, has_l, has_r, pol);
    Win wm = make_win(rm, lane, right_edge);
    Win wc = make_win(rc, lane, right_edge);

#pragma unroll
    for (int i = 0; i < RPT; i++) {
        const int r = row0 + i;
        // Prefetch row r+2 first; latency covered by this iteration's compute+store.
        Raw rn = load_raw<CHECK>(pp, r + 2, x_eff, has_l, has_r, pol);
        // Resolve window for row r+1 (raw loaded last iteration).
        Win wp = make_win(rp, lane, right_edge);

        float t0, t1, t2, t3;
        float m0, m1, m2, m3;
        float b0, b1, b2, b3;
        row_contrib(wm, k00, k01, k02, t0, t1, t2, t3);
        row_contrib(wc, k10, k11, k12, m0, m1, m2, m3);
        row_contrib(wp, k20, k21, k22, b0, b1, b2, b3);

        if (active) {
            float4 o;
            o.x = fmax3(t0, m0, b0);
            o.y = fmax3(t1, m1, b1);
            o.z = fmax3(t2, m2, b2);
            o.w = fmax3(t3, m3, b3);
            // Streaming store: evict-first in L2, minimizes displacement of x.
            __stcs(reinterpret_cast<float4*>(op + r * XW + x_eff * 4), o);
        }
        wm = wc; wc = wp; rp = rn;
    }
}

__global__ __launch_bounds__(128) void tropical_conv3x3_r11(
    const float* __restrict__ x,
    const float* __restrict__ kern,
    float* __restrict__ out)
{
    const int plane = blockIdx.x / STRIPS;             // b*C + c
    const int strip = blockIdx.x % STRIPS;
    const int tx    = threadIdx.x;                      // 0..63
    const int lane  = tx & 31;
    const int x_eff = (tx < W4) ? tx : (W4 - 1);
    const bool active     = (tx < W4);
    const bool right_edge = (x_eff >= W4 - 1);
    const bool has_l = (lane == 0)  && (x_eff > 0);
    const bool has_r = (lane == 31) && (x_eff < W4 - 1);
    const int row0  = strip * ROWS_PER_BLOCK + threadIdx.y * RPT;

    const unsigned long long pol = mk_evict_last_policy();

    const int c = plane & (XC - 1);
    const float* kc = kern + c * 9;
    const float k00 = __ldg(kc + 0), k01 = __ldg(kc + 1), k02 = __ldg(kc + 2);
    const float k10 = __ldg(kc + 3), k11 = __ldg(kc + 4), k12 = __ldg(kc + 5);
    const float k20 = __ldg(kc + 6), k21 = __ldg(kc + 7), k22 = __ldg(kc + 8);

    const float* pp = x   + (size_t)plane * (XH * XW);
    float*       op = out + (size_t)plane * (XH * XW);

    if (strip == 0 || strip == STRIPS - 1) {
        run_strip<true >(pp, op, row0, x_eff, lane, active, right_edge, has_l, has_r, pol,
                         k00, k01, k02, k10, k11, k12, k20, k21, k22);
    } else {
        run_strip<false>(pp, op, row0, x_eff, lane, active, right_edge, has_l, has_r, pol,
                         k00, k01, k02, k10, k11, k12, k20, k21, k22);
    }
}

extern "C" void kernel_launch(void* const* d_in, const int* in_sizes, int n_in,
                              void* d_out, int out_size)
{
    const float* x = (const float*)d_in[0];
    const float* k = (const float*)d_in[1];
    float* out = (float*)d_out;

    dim3 block(64, BY, 1);                               // 128 threads
    dim3 grid(XB * XC * STRIPS, 1, 1);                   // 512 * 14 = 7168 blocks
    tropical_conv3x3_r11<<<grid, block>>>(x, k, out);
}

// round 12
// speedup vs baseline: 1.0049x; 1.0049x over previous
#include <cuda_runtime.h>
#include <math_constants.h>

// TropicalConv2D (max-plus 3x3 depthwise), x:(8,64,224,224) f32, k:(64,1,3,3), s=1,p=1,d=1.
// R12: R9 structure with 100% lane utilization: tid -> (cg = tid%56, ro = tid/56),
//      224-thread blocks (7 warps), no idle lanes. Shuffle halos valid because cg-wrap
//      lanes coincide with image edges (-inf) and warp-boundary lanes use seam loads.

#define XB 8
#define XC 64
#define XH 224
#define XW 224
#define W4 56          // float4 groups per row
#define RPT 8          // output rows per thread
#define RO_N 4         // row sub-strips per block
#define ROWS_PER_BLOCK (RPT * RO_N)             // 32
#define STRIPS (XH / ROWS_PER_BLOCK)            // 7
#define NTHREADS (W4 * RO_N)                    // 224

#define NEG_INF (-CUDART_INF_F)

__device__ __forceinline__ float fmax3(float a, float b, float c) {
    float d;
    asm("max.f32 %0, %1, %2, %3;" : "=f"(d) : "f"(a), "f"(b), "f"(c));
    return d;
}

struct Raw { float v0, v1, v2, v3, l, r; };
struct Win { float w[6]; };   // wl, v0..v3, wr

__device__ __forceinline__ Raw neg_raw() {
    Raw w; w.v0 = w.v1 = w.v2 = w.v3 = w.l = w.r = NEG_INF; return w;
}

// Load stage. CHECK=false (interior strips): no row-range test, no neg_raw path.
template<bool CHECK>
__device__ __forceinline__ Raw load_raw(const float* __restrict__ colbase, int r,
                                        bool has_l, bool has_r) {
    if (CHECK) { if (r < 0 || r >= XH) return neg_raw(); }
    const float* rp = colbase + r * XW;
    float4 v = *reinterpret_cast<const float4*>(rp);
    Raw w;
    w.v0 = v.x; w.v1 = v.y; w.v2 = v.z; w.v3 = v.w;
    w.l = has_l ? __ldg(rp - 1) : NEG_INF;
    w.r = has_r ? __ldg(rp + 4) : NEG_INF;
    return w;
}

// Window stage: 2 SHFL + overrides.
//  - lane 0/31: seam value from scalar load (or -inf if at image edge, folded into w.l/w.r)
//  - cg==0 / cg==55: true image edge -> -inf (also fixes wrong-row shuffle at cg wrap)
__device__ __forceinline__ Win make_win(const Raw& w, int lane, bool left_edge, bool right_edge) {
    Win o;
    o.w[1] = w.v0; o.w[2] = w.v1; o.w[3] = w.v2; o.w[4] = w.v3;
    float wl = __shfl_up_sync(0xffffffffu,   w.v3, 1);
    float wr = __shfl_down_sync(0xffffffffu, w.v0, 1);
    if (lane == 0)  wl = w.l;
    if (lane == 31) wr = w.r;
    o.w[0] = left_edge  ? NEG_INF : wl;
    o.w[5] = right_edge ? NEG_INF : wr;
    return o;
}

// Per-window-row horizontal contribution: 3 FADD + 1 FMNMX3 per output.
__device__ __forceinline__ void row_contrib(const Win& w, float k0, float k1, float k2,
                                            float& r0, float& r1, float& r2, float& r3) {
    r0 = fmax3(w.w[0] + k0, w.w[1] + k1, w.w[2] + k2);
    r1 = fmax3(w.w[1] + k0, w.w[2] + k1, w.w[3] + k2);
    r2 = fmax3(w.w[2] + k0, w.w[3] + k1, w.w[4] + k2);
    r3 = fmax3(w.w[3] + k0, w.w[4] + k1, w.w[5] + k2);
}

template<bool CHECK>
__device__ __forceinline__ void run_strip(
    const float* __restrict__ colbase, float* __restrict__ ocol,
    int row0, int lane, bool left_edge, bool right_edge,
    bool has_l, bool has_r,
    float k00, float k01, float k02,
    float k10, float k11, float k12,
    float k20, float k21, float k22)
{
    // Prologue: three independent loads in flight, then resolve first two windows.
    Raw rm = load_raw<CHECK>(colbase, row0 - 1, has_l, has_r);
    Raw rc = load_raw<CHECK>(colbase, row0,     has_l, has_r);
    Raw rp = load_raw<CHECK>(colbase, row0 + 1, has_l, has_r);
    Win wm = make_win(rm, lane, left_edge, right_edge);
    Win wc = make_win(rc, lane, left_edge, right_edge);

#pragma unroll
    for (int i = 0; i < RPT; i++) {
        const int r = row0 + i;
        // Prefetch row r+2 first; latency covered by this iteration's compute+store.
        Raw rn = load_raw<CHECK>(colbase, r + 2, has_l, has_r);
        // Resolve window for row r+1 (raw loaded last iteration).
        Win wp = make_win(rp, lane, left_edge, right_edge);

        float t0, t1, t2, t3;
        float m0, m1, m2, m3;
        float b0, b1, b2, b3;
        row_contrib(wm, k00, k01, k02, t0, t1, t2, t3);
        row_contrib(wc, k10, k11, k12, m0, m1, m2, m3);
        row_contrib(wp, k20, k21, k22, b0, b1, b2, b3);

        float4 o;
        o.x = fmax3(t0, m0, b0);
        o.y = fmax3(t1, m1, b1);
        o.z = fmax3(t2, m2, b2);
        o.w = fmax3(t3, m3, b3);
        __stwt(reinterpret_cast<float4*>(ocol + r * XW), o);

        wm = wc; wc = wp; rp = rn;
    }
}

__global__ __launch_bounds__(NTHREADS) void tropical_conv3x3_r12(
    const float* __restrict__ x,
    const float* __restrict__ kern,
    float* __restrict__ out)
{
    const int plane = blockIdx.x / STRIPS;             // b*C + c
    const int strip = blockIdx.x % STRIPS;
    const int tid   = threadIdx.x;                      // 0..223
    const int lane  = tid & 31;
    const int cg    = tid % W4;                         // column group 0..55
    const int ro    = tid / W4;                         // row sub-strip 0..3
    const bool left_edge  = (cg == 0);
    const bool right_edge = (cg == W4 - 1);
    const bool has_l = (lane == 0)  && !left_edge;
    const bool has_r = (lane == 31) && !right_edge;
    const int row0  = strip * ROWS_PER_BLOCK + ro * RPT;

    const int c = plane & (XC - 1);
    const float* kc = kern + c * 9;
    const float k00 = __ldg(kc + 0), k01 = __ldg(kc + 1), k02 = __ldg(kc + 2);
    const float k10 = __ldg(kc + 3), k11 = __ldg(kc + 4), k12 = __ldg(kc + 5);
    const float k20 = __ldg(kc + 6), k21 = __ldg(kc + 7), k22 = __ldg(kc + 8);

    const float* colbase = x   + (size_t)plane * (XH * XW) + cg * 4;
    float*       ocol    = out + (size_t)plane * (XH * XW) + cg * 4;

    if (strip == 0 || strip == STRIPS - 1) {
        run_strip<true >(colbase, ocol, row0, lane, left_edge, right_edge, has_l, has_r,
                         k00, k01, k02, k10, k11, k12, k20, k21, k22);
    } else {
        run_strip<false>(colbase, ocol, row0, lane, left_edge, right_edge, has_l, has_r,
                         k00, k01, k02, k10, k11, k12, k20, k21, k22);
    }
}

extern "C" void kernel_launch(void* const* d_in, const int* in_sizes, int n_in,
                              void* d_out, int out_size)
{
    const float* x = (const float*)d_in[0];
    const float* k = (const float*)d_in[1];
    float* out = (float*)d_out;

    dim3 block(NTHREADS, 1, 1);                          // 224 threads (7 warps)
    dim3 grid(XB * XC * STRIPS, 1, 1);                   // 512 * 7 = 3584 blocks
    tropical_conv3x3_r12<<<grid, block>>>(x, k, out);
}

// round 13
// speedup vs baseline: 1.0139x; 1.0090x over previous
#include <cuda_runtime.h>
#include <math_constants.h>

// TropicalConv2D (max-plus 3x3 depthwise), x:(8,64,224,224) f32, k:(64,1,3,3), s=1,p=1,d=1.
// R13: R9 structure (best known: 64-lane coalesced layout, interior/boundary templates,
//      fmax3, pipelined loads, __stwt) with RPT=16 (10% fewer loads) and 3584 blocks.

#define XB 8
#define XC 64
#define XH 224
#define XW 224
#define W4 56          // float4 groups per row
#define RPT 16         // output rows per thread
#define BY 2           // row strips per block
#define ROWS_PER_BLOCK (RPT * BY)               // 32
#define STRIPS (XH / ROWS_PER_BLOCK)            // 7

#define NEG_INF (-CUDART_INF_F)

__device__ __forceinline__ float fmax3(float a, float b, float c) {
    float d;
    asm("max.f32 %0, %1, %2, %3;" : "=f"(d) : "f"(a), "f"(b), "f"(c));
    return d;
}

struct Raw { float v0, v1, v2, v3, l, r; };
struct Win { float w[6]; };   // wl, v0..v3, wr

__device__ __forceinline__ Raw neg_raw() {
    Raw w; w.v0 = w.v1 = w.v2 = w.v3 = w.l = w.r = NEG_INF; return w;
}

// Load stage. CHECK=false (interior strips): no row-range test, no neg_raw path.
template<bool CHECK>
__device__ __forceinline__ Raw load_raw(const float* __restrict__ pp, int r,
                                        int x_eff, bool has_l, bool has_r) {
    if (CHECK) { if (r < 0 || r >= XH) return neg_raw(); }
    const float* rp = pp + r * XW + x_eff * 4;
    float4 v = *reinterpret_cast<const float4*>(rp);
    Raw w;
    w.v0 = v.x; w.v1 = v.y; w.v2 = v.z; w.v3 = v.w;
    w.l = has_l ? __ldg(rp - 1) : NEG_INF;
    w.r = has_r ? __ldg(rp + 4) : NEG_INF;
    return w;
}

// Window stage: 2 SHFL + 2 SEL (+1 loop-invariant edge SEL).
__device__ __forceinline__ Win make_win(const Raw& w, int lane, bool right_edge) {
    Win o;
    o.w[1] = w.v0; o.w[2] = w.v1; o.w[3] = w.v2; o.w[4] = w.v3;
    float wl = __shfl_up_sync(0xffffffffu,   w.v3, 1);
    float wr = __shfl_down_sync(0xffffffffu, w.v0, 1);
    o.w[0] = (lane == 0)  ? w.l : wl;
    o.w[5] = (lane == 31) ? w.r : wr;
    if (right_edge) o.w[5] = NEG_INF;
    return o;
}

// Per-window-row horizontal contribution: 3 FADD + 1 FMNMX3 per output.
__device__ __forceinline__ void row_contrib(const Win& w, float k0, float k1, float k2,
                                            float& r0, float& r1, float& r2, float& r3) {
    r0 = fmax3(w.w[0] + k0, w.w[1] + k1, w.w[2] + k2);
    r1 = fmax3(w.w[1] + k0, w.w[2] + k1, w.w[3] + k2);
    r2 = fmax3(w.w[2] + k0, w.w[3] + k1, w.w[4] + k2);
    r3 = fmax3(w.w[3] + k0, w.w[4] + k1, w.w[5] + k2);
}

template<bool CHECK>
__device__ __forceinline__ void run_strip(
    const float* __restrict__ pp, float* __restrict__ op,
    int row0, int x_eff, int lane, bool active, bool right_edge,
    bool has_l, bool has_r,
    float k00, float k01, float k02,
    float k10, float k11, float k12,
    float k20, float k21, float k22)
{
    // Prologue: three independent loads in flight, then resolve first two windows.
    Raw rm = load_raw<CHECK>(pp, row0 - 1, x_eff, has_l, has_r);
    Raw rc = load_raw<CHECK>(pp, row0,     x_eff, has_l, has_r);
    Raw rp = load_raw<CHECK>(pp, row0 + 1, x_eff, has_l, has_r);
    Win wm = make_win(rm, lane, right_edge);
    Win wc = make_win(rc, lane, right_edge);

#pragma unroll
    for (int i = 0; i < RPT; i++) {
        const int r = row0 + i;
        // Prefetch row r+2 first; latency covered by this iteration's compute+store.
        Raw rn = load_raw<CHECK>(pp, r + 2, x_eff, has_l, has_r);
        // Resolve window for row r+1 (raw loaded last iteration).
        Win wp = make_win(rp, lane, right_edge);

        float t0, t1, t2, t3;
        float m0, m1, m2, m3;
        float b0, b1, b2, b3;
        row_contrib(wm, k00, k01, k02, t0, t1, t2, t3);
        row_contrib(wc, k10, k11, k12, m0, m1, m2, m3);
        row_contrib(wp, k20, k21, k22, b0, b1, b2, b3);

        if (active) {
            float4 o;
            o.x = fmax3(t0, m0, b0);
            o.y = fmax3(t1, m1, b1);
            o.z = fmax3(t2, m2, b2);
            o.w = fmax3(t3, m3, b3);
            __stwt(reinterpret_cast<float4*>(op + r * XW + x_eff * 4), o);
        }
        wm = wc; wc = wp; rp = rn;
    }
}

__global__ __launch_bounds__(128) void tropical_conv3x3_r13(
    const float* __restrict__ x,
    const float* __restrict__ kern,
    float* __restrict__ out)
{
    const int plane = blockIdx.x / STRIPS;             // b*C + c
    const int strip = blockIdx.x % STRIPS;
    const int tx    = threadIdx.x;                      // 0..63
    const int lane  = tx & 31;
    const int x_eff = (tx < W4) ? tx : (W4 - 1);
    const bool active     = (tx < W4);
    const bool right_edge = (x_eff >= W4 - 1);
    const bool has_l = (lane == 0)  && (x_eff > 0);
    const bool has_r = (lane == 31) && (x_eff < W4 - 1);
    const int row0  = strip * ROWS_PER_BLOCK + threadIdx.y * RPT;

    const int c = plane & (XC - 1);
    const float* kc = kern + c * 9;
    const float k00 = __ldg(kc + 0), k01 = __ldg(kc + 1), k02 = __ldg(kc + 2);
    const float k10 = __ldg(kc + 3), k11 = __ldg(kc + 4), k12 = __ldg(kc + 5);
    const float k20 = __ldg(kc + 6), k21 = __ldg(kc + 7), k22 = __ldg(kc + 8);

    const float* pp = x   + (size_t)plane * (XH * XW);
    float*       op = out + (size_t)plane * (XH * XW);

    if (strip == 0 || strip == STRIPS - 1) {
        run_strip<true >(pp, op, row0, x_eff, lane, active, right_edge, has_l, has_r,
                         k00, k01, k02, k10, k11, k12, k20, k21, k22);
    } else {
        run_strip<false>(pp, op, row0, x_eff, lane, active, right_edge, has_l, has_r,
                         k00, k01, k02, k10, k11, k12, k20, k21, k22);
    }
}

extern "C" void kernel_launch(void* const* d_in, const int* in_sizes, int n_in,
                              void* d_out, int out_size)
{
    const float* x = (const float*)d_in[0];
    const float* k = (const float*)d_in[1];
    float* out = (float*)d_out;

    dim3 block(64, BY, 1);                               // 128 threads
    dim3 grid(XB * XC * STRIPS, 1, 1);                   // 512 * 7 = 3584 blocks
    tropical_conv3x3_r13<<<grid, block>>>(x, k, out);
}

// round 14
// speedup vs baseline: 1.0591x; 1.0445x over previous
#include <cuda_runtime.h>
#include <math_constants.h>

// TropicalConv2D (max-plus 3x3 depthwise), x:(8,64,224,224) f32, k:(64,1,3,3), s=1,p=1,d=1.
// R14: warp-per-row 8-wide layout (28 lanes x 8 floats = full row, zero seam loads,
//      2 SHFL/row) + R9 machinery: fmax3, interior/boundary templates, depth-1
//      pipeline, 128-thread blocks, __stwt.

#define XB 8
#define XC 64
#define XH 224
#define XW 224
#define LANES 28       // active lanes (28*8 = 224 = full row)
#define RPT 8          // output rows per warp per strip pass
#define WY 4           // warps per block
#define ROWS_PER_BLOCK (RPT * WY)               // 32
#define STRIPS (XH / ROWS_PER_BLOCK)            // 7

#define NEG_INF (-CUDART_INF_F)

__device__ __forceinline__ float fmax3(float a, float b, float c) {
    float d;
    asm("max.f32 %0, %1, %2, %3;" : "=f"(d) : "f"(a), "f"(b), "f"(c));
    return d;
}

struct Raw { float v[8]; };      // 8 contiguous floats (2 x LDG.128)
struct Win { float w[10]; };     // wl + 8 + wr

__device__ __forceinline__ Raw neg_raw() {
    Raw r;
#pragma unroll
    for (int i = 0; i < 8; i++) r.v[i] = NEG_INF;
    return r;
}

// Load stage: 2 independent LDG.128. No seam scalars (halos = image edges).
// CHECK=false (interior strips): no row-range test.
template<bool CHECK>
__device__ __forceinline__ Raw load_raw(const float* __restrict__ rowbase, int r) {
    if (CHECK) { if (r < 0 || r >= XH) return neg_raw(); }
    const float* rp = rowbase + r * XW;
    float4 a = *reinterpret_cast<const float4*>(rp);
    float4 b = *reinterpret_cast<const float4*>(rp + 4);
    Raw w;
    w.v[0] = a.x; w.v[1] = a.y; w.v[2] = a.z; w.v[3] = a.w;
    w.v[4] = b.x; w.v[5] = b.y; w.v[6] = b.z; w.v[7] = b.w;
    return w;
}

// Window stage: 2 SHFL + 2 edge SELs. Both halos at warp ends are image edges.
__device__ __forceinline__ Win make_win(const Raw& r, int lane) {
    Win o;
#pragma unroll
    for (int i = 0; i < 8; i++) o.w[i + 1] = r.v[i];
    float wl = __shfl_up_sync(0xffffffffu,   r.v[7], 1);
    float wr = __shfl_down_sync(0xffffffffu, r.v[0], 1);
    o.w[0] = (lane == 0) ? NEG_INF : wl;
    o.w[9] = (lane >= LANES - 1) ? NEG_INF : wr;
    return o;
}

// Per-window-row contribution: 8 outputs, each 3 FADD + 1 FMNMX3.
__device__ __forceinline__ void row_contrib(const Win& w, float k0, float k1, float k2,
                                            float* r) {
#pragma unroll
    for (int j = 0; j < 8; j++)
        r[j] = fmax3(w.w[j] + k0, w.w[j + 1] + k1, w.w[j + 2] + k2);
}

template<bool CHECK>
__device__ __forceinline__ void run_strip(
    const float* __restrict__ rowbase, float* __restrict__ orow,
    int row0, int lane, bool active,
    float k00, float k01, float k02,
    float k10, float k11, float k12,
    float k20, float k21, float k22)
{
    // Prologue: three independent row loads (6 LDG.128) in flight.
    Raw rm = load_raw<CHECK>(rowbase, row0 - 1);
    Raw rc = load_raw<CHECK>(rowbase, row0);
    Raw rp = load_raw<CHECK>(rowbase, row0 + 1);
    Win wm = make_win(rm, lane);
    Win wc = make_win(rc, lane);

#pragma unroll
    for (int i = 0; i < RPT; i++) {
        const int r = row0 + i;
        // Prefetch row r+2 first; latency covered by this iteration's compute+store.
        Raw rn = load_raw<CHECK>(rowbase, r + 2);
        // Resolve window for row r+1 (raw loaded last iteration).
        Win wp = make_win(rp, lane);

        float t[8], m[8], b[8];
        row_contrib(wm, k00, k01, k02, t);
        row_contrib(wc, k10, k11, k12, m);
        row_contrib(wp, k20, k21, k22, b);

        if (active) {
            float4 o0, o1;
            o0.x = fmax3(t[0], m[0], b[0]);
            o0.y = fmax3(t[1], m[1], b[1]);
            o0.z = fmax3(t[2], m[2], b[2]);
            o0.w = fmax3(t[3], m[3], b[3]);
            o1.x = fmax3(t[4], m[4], b[4]);
            o1.y = fmax3(t[5], m[5], b[5]);
            o1.z = fmax3(t[6], m[6], b[6]);
            o1.w = fmax3(t[7], m[7], b[7]);
            float* dst = orow + r * XW;
            __stwt(reinterpret_cast<float4*>(dst),     o0);
            __stwt(reinterpret_cast<float4*>(dst + 4), o1);
        }
        wm = wc; wc = wp; rp = rn;
    }
}

__global__ __launch_bounds__(128) void tropical_conv3x3_r14(
    const float* __restrict__ x,
    const float* __restrict__ kern,
    float* __restrict__ out)
{
    const int plane = blockIdx.x / STRIPS;             // b*C + c
    const int strip = blockIdx.x % STRIPS;
    const int lane  = threadIdx.x;                      // 0..31
    const int xl    = (lane < LANES) ? lane : (LANES - 1);   // clamp dup lanes
    const bool active = (lane < LANES);
    const int row0  = strip * ROWS_PER_BLOCK + threadIdx.y * RPT;

    const int c = plane & (XC - 1);
    const float* kc = kern + c * 9;
    const float k00 = __ldg(kc + 0), k01 = __ldg(kc + 1), k02 = __ldg(kc + 2);
    const float k10 = __ldg(kc + 3), k11 = __ldg(kc + 4), k12 = __ldg(kc + 5);
    const float k20 = __ldg(kc + 6), k21 = __ldg(kc + 7), k22 = __ldg(kc + 8);

    const float* rowbase = x   + (size_t)plane * (XH * XW) + xl * 8;
    float*       orow    = out + (size_t)plane * (XH * XW) + xl * 8;

    if (strip == 0 || strip == STRIPS - 1) {
        run_strip<true >(rowbase, orow, row0, lane, active,
                         k00, k01, k02, k10, k11, k12, k20, k21, k22);
    } else {
        run_strip<false>(rowbase, orow, row0, lane, active,
                         k00, k01, k02, k10, k11, k12, k20, k21, k22);
    }
}

extern "C" void kernel_launch(void* const* d_in, const int* in_sizes, int n_in,
                              void* d_out, int out_size)
{
    const float* x = (const float*)d_in[0];
    const float* k = (const float*)d_in[1];
    float* out = (float*)d_out;

    dim3 block(32, WY, 1);                               // 128 threads
    dim3 grid(XB * XC * STRIPS, 1, 1);                   // 512 * 7 = 3584 blocks
    tropical_conv3x3_r14<<<grid, block>>>(x, k, out);
}